// round 2
// baseline (speedup 1.0000x reference)
#include <cuda_runtime.h>
#include <cuda_bf16.h>
#include <cstdint>

#define TOKENS 8192
#define DMODEL 1024
#define VOCAB  32000
#define MTILE  128
#define NTILE  256
#define KC     64                 // bf16 per K-chunk (128 B rows)
#define NCHUNKS (DMODEL / KC)     // 16
#define NSTAGES 3
#define NTILES_N (VOCAB / NTILE)  // 125

// -------- scratch (device globals: allocation-free rule) --------
__device__ __nv_bfloat16 g_xb[TOKENS * DMODEL];        // 16 MB
__device__ __nv_bfloat16 g_wb[(size_t)VOCAB * DMODEL]; // 64 MB
__device__ float g_tscore[TOKENS];
__device__ float g_partials[NTILES_N * TOKENS];        // 4 MB

// -------- helpers --------
__device__ __forceinline__ uint32_t smem_u32(const void* p) {
    uint32_t a;
    asm("{ .reg .u64 t; cvta.to.shared.u64 t, %1; cvt.u32.u64 %0, t; }"
        : "=r"(a) : "l"(p));
    return a;
}
__device__ __forceinline__ uint32_t swz(uint32_t off) {   // SW128: bits[6:4] ^= bits[9:7]
    return off ^ ((off >> 3) & 0x70);
}

// -------- kernel 1: fp32 -> bf16 conversion --------
__global__ void cvt_x_kernel(const float* __restrict__ src) {
    int i = blockIdx.x * blockDim.x + threadIdx.x;
    int stride = gridDim.x * blockDim.x;
    int n4 = TOKENS * DMODEL / 4;
    for (; i < n4; i += stride) {
        float4 v = ((const float4*)src)[i];
        ((__nv_bfloat162*)g_xb)[2 * i]     = __floats2bfloat162_rn(v.x, v.y);
        ((__nv_bfloat162*)g_xb)[2 * i + 1] = __floats2bfloat162_rn(v.z, v.w);
    }
}
__global__ void cvt_w_kernel(const float* __restrict__ src) {
    size_t i = (size_t)blockIdx.x * blockDim.x + threadIdx.x;
    size_t stride = (size_t)gridDim.x * blockDim.x;
    size_t n4 = (size_t)VOCAB * DMODEL / 4;
    for (; i < n4; i += stride) {
        float4 v = ((const float4*)src)[i];
        ((__nv_bfloat162*)g_wb)[2 * i]     = __floats2bfloat162_rn(v.x, v.y);
        ((__nv_bfloat162*)g_wb)[2 * i + 1] = __floats2bfloat162_rn(v.z, v.w);
    }
}

// -------- kernel 2: exact fp32 target score --------
__global__ void tscore_kernel(const float* __restrict__ x,
                              const float* __restrict__ w,
                              const int* __restrict__ tgt) {
    int t = blockIdx.x;
    const float4* xr = (const float4*)(x + (size_t)t * DMODEL);
    const float4* wr = (const float4*)(w + (size_t)tgt[t] * DMODEL);
    float s = 0.f;
    for (int i = threadIdx.x; i < DMODEL / 4; i += blockDim.x) {
        float4 a = xr[i], b = wr[i];
        s += a.x * b.x; s += a.y * b.y; s += a.z * b.z; s += a.w * b.w;
    }
#pragma unroll
    for (int o = 16; o; o >>= 1) s += __shfl_xor_sync(0xFFFFFFFFu, s, o);
    __shared__ float ws[4];
    if ((threadIdx.x & 31) == 0) ws[threadIdx.x >> 5] = s;
    __syncthreads();
    if (threadIdx.x == 0) g_tscore[t] = ws[0] + ws[1] + ws[2] + ws[3];
}

// -------- kernel 3: main GEMM (mma.sync bf16) + row exp-sum --------
// smem: 3 stages x [A 128x128B | B 256x128B] = 3 x 48KB, 1KB-aligned.
__device__ __forceinline__ void load_chunk(const __nv_bfloat16* xrow,
                                           const __nv_bfloat16* wrow,
                                           int c, uint32_t stA, int tid) {
    const char* asrc = (const char*)xrow + (size_t)c * KC * 2;
    const char* bsrc = (const char*)wrow + (size_t)c * KC * 2;
    uint32_t stB = stA + MTILE * 128;
#pragma unroll
    for (int j = 0; j < 2; ++j) {            // A: 128 rows x 8 segs of 16B
        int l = tid + 512 * j;
        int row = l >> 3, seg = l & 7;
        uint32_t dst = stA + swz((uint32_t)(row * 128 + seg * 16));
        const char* src = asrc + (size_t)row * (DMODEL * 2) + seg * 16;
        asm volatile("cp.async.cg.shared.global [%0], [%1], 16;" :: "r"(dst), "l"(src));
    }
#pragma unroll
    for (int j = 0; j < 4; ++j) {            // B: 256 rows x 8 segs of 16B
        int l = tid + 512 * j;
        int row = l >> 3, seg = l & 7;
        uint32_t dst = stB + swz((uint32_t)(row * 128 + seg * 16));
        const char* src = bsrc + (size_t)row * (DMODEL * 2) + seg * 16;
        asm volatile("cp.async.cg.shared.global [%0], [%1], 16;" :: "r"(dst), "l"(src));
    }
}

__global__ void __launch_bounds__(512, 1) mevo_main_kernel() {
    extern __shared__ char sm[];
    const uint32_t STAGE = (MTILE + NTILE) * 128;   // 49152
    uint32_t raw  = smem_u32(sm);
    uint32_t base = (raw + 1023u) & ~1023u;

    int tid = threadIdx.x;
    int wid = tid >> 5, lid = tid & 31;
    int wm = wid & 3, wn = wid >> 2;        // 4x4 warp grid
    int m0 = blockIdx.x * MTILE;
    int ny = blockIdx.y;
    int n0 = ny * NTILE;

    const __nv_bfloat16* xrow = g_xb + (size_t)m0 * DMODEL;
    const __nv_bfloat16* wrow = g_wb + (size_t)n0 * DMODEL;

    float acc[2][8][4];
#pragma unroll
    for (int i = 0; i < 2; ++i)
#pragma unroll
        for (int j = 0; j < 8; ++j)
#pragma unroll
            for (int k = 0; k < 4; ++k) acc[i][j][k] = 0.f;

    // lane-invariant address pieces
    const int rbase  = wm * 32;
    const int nbase  = wn * 64;
    const int arow_l = lid & 15;
    const uint32_t akb_l = (uint32_t)((lid >> 4) << 4);
    const int brow_l = lid & 7;
    const uint32_t bkb_l = (uint32_t)(((lid >> 3) & 1) << 4);

    // prologue: fill 3 stages
#pragma unroll
    for (int s = 0; s < NSTAGES; ++s) {
        load_chunk(xrow, wrow, s, base + s * STAGE, tid);
        asm volatile("cp.async.commit_group;" ::: "memory");
    }

    for (int c = 0; c < NCHUNKS; ++c) {
        int st = c % NSTAGES;
        uint32_t Ab = base + st * STAGE;
        uint32_t Bb = Ab + MTILE * 128;

        asm volatile("cp.async.wait_group 2;" ::: "memory");
        __syncthreads();

        // compute this chunk: 4 k16 steps
#pragma unroll
        for (int s = 0; s < 4; ++s) {
            uint32_t kb = (uint32_t)(s * 32);
            uint32_t a[2][4];
#pragma unroll
            for (int mf = 0; mf < 2; ++mf) {
                uint32_t addr = Ab + swz((uint32_t)((rbase + mf * 16 + arow_l) * 128)
                                         + kb + akb_l);
                asm volatile("ldmatrix.sync.aligned.m8n8.x4.shared.b16 "
                             "{%0,%1,%2,%3}, [%4];"
                             : "=r"(a[mf][0]), "=r"(a[mf][1]),
                               "=r"(a[mf][2]), "=r"(a[mf][3])
                             : "r"(addr));
            }
            uint32_t b[8][2];
#pragma unroll
            for (int nf = 0; nf < 8; ++nf) {
                uint32_t addr = Bb + swz((uint32_t)((nbase + nf * 8 + brow_l) * 128)
                                         + kb + bkb_l);
                asm volatile("ldmatrix.sync.aligned.m8n8.x2.shared.b16 "
                             "{%0,%1}, [%2];"
                             : "=r"(b[nf][0]), "=r"(b[nf][1])
                             : "r"(addr));
            }
#pragma unroll
            for (int mf = 0; mf < 2; ++mf)
#pragma unroll
                for (int nf = 0; nf < 8; ++nf)
                    asm volatile(
                        "mma.sync.aligned.m16n8k16.row.col.f32.bf16.bf16.f32 "
                        "{%0,%1,%2,%3}, {%4,%5,%6,%7}, {%8,%9}, {%0,%1,%2,%3};"
                        : "+f"(acc[mf][nf][0]), "+f"(acc[mf][nf][1]),
                          "+f"(acc[mf][nf][2]), "+f"(acc[mf][nf][3])
                        : "r"(a[mf][0]), "r"(a[mf][1]), "r"(a[mf][2]), "r"(a[mf][3]),
                          "r"(b[nf][0]), "r"(b[nf][1]));
        }

        __syncthreads();
        if (c + NSTAGES < NCHUNKS)
            load_chunk(xrow, wrow, c + NSTAGES, Ab, tid);
        asm volatile("cp.async.commit_group;" ::: "memory");
    }

    // ---- epilogue: exp-sum each of this CTA's 128 rows ----
    float rs[2][2];
#pragma unroll
    for (int mf = 0; mf < 2; ++mf) { rs[mf][0] = 0.f; rs[mf][1] = 0.f; }
#pragma unroll
    for (int mf = 0; mf < 2; ++mf)
#pragma unroll
        for (int nf = 0; nf < 8; ++nf) {
            rs[mf][0] += __expf(acc[mf][nf][0]) + __expf(acc[mf][nf][1]);
            rs[mf][1] += __expf(acc[mf][nf][2]) + __expf(acc[mf][nf][3]);
        }
#pragma unroll
    for (int mf = 0; mf < 2; ++mf)
#pragma unroll
        for (int h = 0; h < 2; ++h) {
            rs[mf][h] += __shfl_xor_sync(0xFFFFFFFFu, rs[mf][h], 1);
            rs[mf][h] += __shfl_xor_sync(0xFFFFFFFFu, rs[mf][h], 2);
        }

    float* buf = (float*)sm;   // reuse stage smem: [4 wn][128 rows]
    __syncthreads();
    if ((lid & 3) == 0) {
        int g = lid >> 2;
#pragma unroll
        for (int mf = 0; mf < 2; ++mf) {
            buf[wn * 128 + rbase + mf * 16 + g]     = rs[mf][0];
            buf[wn * 128 + rbase + mf * 16 + g + 8] = rs[mf][1];
        }
    }
    __syncthreads();
    if (tid < MTILE) {
        float t = buf[tid] + buf[128 + tid] + buf[256 + tid] + buf[384 + tid];
        g_partials[(size_t)ny * TOKENS + m0 + tid] = t;
    }
}

// -------- kernel 4: finalize --------
__global__ void finalize_kernel(float* __restrict__ out) {
    __shared__ float red[256];
    float acc = 0.f;
    for (int r = threadIdx.x; r < TOKENS; r += 256) {
        float s = 0.f;
        for (int p = 0; p < NTILES_N; ++p) s += g_partials[(size_t)p * TOKENS + r];
        acc += logf(s) - g_tscore[r];
    }
    red[threadIdx.x] = acc;
    __syncthreads();
    for (int o = 128; o; o >>= 1) {
        if (threadIdx.x < o) red[threadIdx.x] += red[threadIdx.x + o];
        __syncthreads();
    }
    if (threadIdx.x == 0) out[0] = red[0];
}

// -------- launch --------
extern "C" void kernel_launch(void* const* d_in, const int* in_sizes, int n_in,
                              void* d_out, int out_size) {
    (void)in_sizes; (void)n_in; (void)out_size;
    const float* x = (const float*)d_in[0];
    const float* w = (const float*)d_in[1];
    const int*   t = (const int*)d_in[2];
    float* out = (float*)d_out;

    const uint32_t STAGE = (MTILE + NTILE) * 128;
    const int SMEM_BYTES = 1024 + NSTAGES * STAGE;

    cudaFuncSetAttribute(mevo_main_kernel,
                         cudaFuncAttributeMaxDynamicSharedMemorySize, SMEM_BYTES);

    cvt_x_kernel<<<2048, 256>>>(x);
    cvt_w_kernel<<<4096, 256>>>(w);
    tscore_kernel<<<TOKENS, 128>>>(x, w, t);
    mevo_main_kernel<<<dim3(TOKENS / MTILE, NTILES_N), 512, SMEM_BYTES>>>();
    finalize_kernel<<<1, 256>>>(out);
}